// round 11
// baseline (speedup 1.0000x reference)
#include <cuda_runtime.h>
#include <cstdint>

#define PPN 100
#define THREADS 256
#define G 4            // pillars per loop iteration

__device__ __forceinline__ uint32_t smem_u32(const void* p) {
    uint32_t a;
    asm("{ .reg .u64 t; cvta.to.shared.u64 t, %1; cvt.u32.u64 %0, t; }" : "=r"(a) : "l"(p));
    return a;
}
__device__ __forceinline__ void cp_async16(uint32_t saddr, const void* g) {
    asm volatile("cp.async.cg.shared.global [%0], [%1], 16;" :: "r"(saddr), "l"(g));
}
__device__ __forceinline__ void cp_commit() { asm volatile("cp.async.commit_group;"); }
__device__ __forceinline__ void cp_wait0()  { asm volatile("cp.async.wait_group 0;"); }

__global__ __launch_bounds__(THREADS, 4) void pfn_kernel(
    const float* __restrict__ px, const float* __restrict__ py,
    const float* __restrict__ pz, const float* __restrict__ pi,
    const int*   __restrict__ nv,
    const float* __restrict__ xs, const float* __restrict__ ys,
    const float* __restrict__ W,  const float* __restrict__ gamma,
    const float* __restrict__ beta, const float* __restrict__ bmean,
    const float* __restrict__ bvar,
    float* __restrict__ out, int P)
{
    // [buf][pillar][array][n]  = 19.2 KB
    __shared__ __align__(16) float sdata[2][G][6][PPN];
    // [0]=wx [1]=wy [2]=wz [3]=wi [4]=wxs [5]=wys [6..8]=mean-weights [9]=bias
    __shared__ float sW[10][32];
    __shared__ float ssum[G][3];
    __shared__ float pmax2[G][8][33];   // [pillar][warp][channel]
    __shared__ float bmax2[G][32];

    const int tid  = threadIdx.x;
    const int wid  = tid >> 5, lane = tid & 31;
    const int stride = gridDim.x * G;

    // ---- fold BN + feature algebra into weights (once per CTA) ----
    if (tid < 32) {
        const float* Wr = W + tid * 9;
        float w0 = Wr[0], w1 = Wr[1], w2 = Wr[2], w3 = Wr[3];
        float w4 = Wr[4], w5 = Wr[5], w6 = Wr[6], w7 = Wr[7], w8 = Wr[8];
        float s = rsqrtf(bvar[tid] + 1e-3f) * gamma[tid];
        sW[0][tid] = (w0 + w4 + w7) * s;
        sW[1][tid] = (w1 + w5 + w8) * s;
        sW[2][tid] = (w2 + w6) * s;
        sW[3][tid] = w3 * s;
        sW[4][tid] = -w7 * s;
        sW[5][tid] = -w8 * s;
        sW[6][tid] = w4 * s;
        sW[7][tid] = w5 * s;
        sW[8][tid] = w6 * s;
        sW[9][tid] = beta[tid] - bmean[tid] * s;
    }

    const float* const srcs[6] = { px, py, pz, pi, xs, ys };

    // staging macro: 600 float4 slots (G pillars x 6 arrays x 25 vec4)
    // thread covers slots tid, tid+256, tid+512
    #define STAGE(BUF, BASE)                                                     \
        _Pragma("unroll")                                                        \
        for (int k = 0; k < 3; k++) {                                            \
            const int slot = tid + k * 256;                                      \
            if (slot < G * 150) {                                                \
                const int pl = slot / 150, r = slot % 150;                       \
                const int a = r / 25, j = r % 25;                                \
                const int pидx = (BASE) + pl;                                    \
                if (pидx < P)                                                    \
                    cp_async16(smem_u32(&sdata[BUF][pl][a][j * 4]),              \
                               srcs[a] + (size_t)pидx * PPN + j * 4);            \
            }                                                                    \
        }                                                                        \
        cp_commit();

    const int pid0 = blockIdx.x * G;

    // ---- prologue: stage group 0 ----
    if (pid0 < P) { STAGE(0, pid0) }
    int nvr[G];
    #pragma unroll
    for (int pl = 0; pl < G; pl++)
        nvr[pl] = (pid0 + pl < P) ? __ldg(nv + pid0 + pl) : 1;
    cp_wait0();
    __syncthreads();

    const int q  = tid & 7;    // channel quad; q == lane & 7
    const int ng = tid >> 3;   // point group
    const int u0 = q * 4;

    // per-point weights in registers; K/b constants read from smem per pillar
    float wx[4], wy[4], wz[4], wi[4], wxs[4], wys[4];
    #pragma unroll
    for (int t = 0; t < 4; t++) {
        const int u = u0 + t;
        wx[t]  = sW[0][u]; wy[t]  = sW[1][u]; wz[t] = sW[2][u];
        wi[t]  = sW[3][u]; wxs[t] = sW[4][u]; wys[t] = sW[5][u];
    }

    int buf = 0;
    for (int pp = pid0; pp < P; pp += stride) {
        const int nxt = pp + stride;

        // ---- prefetch next group (async, overlaps whole iteration) ----
        if (nxt < P) { STAGE(buf ^ 1, nxt) }
        int nvn[G];
        #pragma unroll
        for (int pl = 0; pl < G; pl++)
            nvn[pl] = (nxt + pl < P) ? __ldg(nv + nxt + pl) : 1;

        // ---- means: 12 half-warps (4 pillars x 3 axes), one barrier ----
        {
            const int hw = tid >> 4, l16 = tid & 15;
            if (hw < 12) {
                const int pl = hw / 3, ax = hw % 3;
                const float* arr = sdata[buf][pl][ax];
                float s = 0.f;
                #pragma unroll
                for (int n = l16; n < PPN; n += 16) s += arr[n];
                #pragma unroll
                for (int o = 8; o; o >>= 1)
                    s += __shfl_down_sync(0xffffffffu, s, o, 16);
                if (l16 == 0) ssum[pl][ax] = s;
            }
        }
        __syncthreads();                                   // B1

        // ---- compute + store channels [0,32) for all G pillars ----
        #pragma unroll
        for (int pl = 0; pl < G; pl++) {
            if (pp + pl >= P) break;
            const int   nvp = nvr[pl];
            const float fnv = (float)nvp;
            const float mx = ssum[pl][0] / fnv;
            const float my = ssum[pl][1] / fnv;
            const float mz = ssum[pl][2] / fnv;

            float K[4], b[4];
            #pragma unroll
            for (int t = 0; t < 4; t++) {
                const int u = u0 + t;
                K[t] = -(mx * sW[6][u] + my * sW[7][u] + mz * sW[8][u]);
                b[t] = sW[9][u];
            }

            float vmax[4] = {0.f, 0.f, 0.f, 0.f};          // post-ReLU >= 0
            float4* out4 = (float4*)(out + (size_t)(pp + pl) * PPN * 64);
            const float (*sd)[PPN] = sdata[buf][pl];

            #pragma unroll
            for (int base = 0; base < PPN; base += 32) {
                const int n = base + ng;
                if (n < PPN) {
                    const float x  = sd[0][n], y  = sd[1][n];
                    const float z  = sd[2][n], it = sd[3][n];
                    const float xv = sd[4][n], yv = sd[5][n];
                    const float m  = (n < nvp) ? 1.f : 0.f;

                    float r[4];
                    #pragma unroll
                    for (int t = 0; t < 4; t++) {
                        float acc = K[t];
                        acc = fmaf(x,  wx[t],  acc);
                        acc = fmaf(y,  wy[t],  acc);
                        acc = fmaf(z,  wz[t],  acc);
                        acc = fmaf(it, wi[t],  acc);
                        acc = fmaf(xv, wxs[t], acc);
                        acc = fmaf(yv, wys[t], acc);
                        r[t] = fmaxf(fmaf(m, acc, b[t]), 0.f);
                        vmax[t] = fmaxf(vmax[t], r[t]);
                    }
                    float4 v; v.x = r[0]; v.y = r[1]; v.z = r[2]; v.w = r[3];
                    __stcs(&out4[(size_t)n * 16 + q], v);
                }
            }

            // intra-warp max over the 4 ng-slots (lane bits 3..4), regs only
            #pragma unroll
            for (int t = 0; t < 4; t++) {
                vmax[t] = fmaxf(vmax[t], __shfl_xor_sync(0xffffffffu, vmax[t], 8));
                vmax[t] = fmaxf(vmax[t], __shfl_xor_sync(0xffffffffu, vmax[t], 16));
            }
            if (lane < 8) {          // lane == q
                #pragma unroll
                for (int t = 0; t < 4; t++)
                    pmax2[pl][wid][lane * 4 + t] = vmax[t];
            }
        }
        __syncthreads();                                   // B2

        // ---- final max: warp pl reduces 8 warp-rows; overlap with cp wait ----
        if (wid < G) {
            float v = pmax2[wid][0][lane];
            #pragma unroll
            for (int w = 1; w < 8; w++) v = fmaxf(v, pmax2[wid][w][lane]);
            bmax2[wid][lane] = v;
        }
        cp_wait0();                  // next group's inputs landed
        __syncthreads();                                   // B3

        // ---- broadcast halves for all G pillars ----
        #pragma unroll
        for (int pl = 0; pl < G; pl++) {
            if (pp + pl >= P) break;
            float4 bc;
            bc.x = bmax2[pl][u0 + 0]; bc.y = bmax2[pl][u0 + 1];
            bc.z = bmax2[pl][u0 + 2]; bc.w = bmax2[pl][u0 + 3];
            float4* out4 = (float4*)(out + (size_t)(pp + pl) * PPN * 64);
            #pragma unroll
            for (int base = 0; base < PPN; base += 32) {
                const int n = base + ng;
                if (n < PPN) __stcs(&out4[(size_t)n * 16 + 8 + q], bc);
            }
        }

        #pragma unroll
        for (int pl = 0; pl < G; pl++) nvr[pl] = nvn[pl];
        buf ^= 1;
    }
    #undef STAGE
}

extern "C" void kernel_launch(void* const* d_in, const int* in_sizes, int n_in,
                              void* d_out, int out_size)
{
    const float* px    = (const float*)d_in[0];
    const float* py    = (const float*)d_in[1];
    const float* pz    = (const float*)d_in[2];
    const float* pi    = (const float*)d_in[3];
    const int*   nv    = (const int*  )d_in[4];
    const float* xs    = (const float*)d_in[5];
    const float* ys    = (const float*)d_in[6];
    // d_in[7] = mask : derivable from num_voxels, not read
    const float* W     = (const float*)d_in[8];
    const float* gamma = (const float*)d_in[9];
    const float* beta  = (const float*)d_in[10];
    const float* bmean = (const float*)d_in[11];
    const float* bvar  = (const float*)d_in[12];

    const int P = in_sizes[4];
    int ctas = 148 * 4;
    const int groups = (P + G - 1) / G;
    if (ctas > groups) ctas = groups;
    pfn_kernel<<<ctas, THREADS>>>(px, py, pz, pi, nv, xs, ys,
                                  W, gamma, beta, bmean, bvar, (float*)d_out, P);
}